// round 1
// baseline (speedup 1.0000x reference)
#include <cuda_runtime.h>
#include <cuda_bf16.h>
#include <math.h>

// Problem dims
#define BB 32
#define TT 64
#define BT 2048           // B*T
#define CC 3
#define HH 32
#define HID 200
#define FEAT 6144

// -------------------- scratch (device globals; no allocs) --------------------
__device__ float g_xt  [BT * 3  * 1024];   // [BT,3,32,32]
__device__ float g_e1  [BT * 8  * 1024];   // [BT,8,32,32]
__device__ float g_e2  [BT * 16 * 256];    // [BT,16,16,16]
__device__ float g_e3  [BT * 32 * 64];     // [BT,32,8,8]
__device__ float g_d2  [BT * 16 * 256];    // [BT,16,16,16]
__device__ float g_d1  [BT * 8  * 1024];   // [BT,8,32,32]
__device__ float g_feat[BT * FEAT];        // [BT,6144]
__device__ float g_h1  [BT * HID];
__device__ float g_h2  [BT * HID];

// -------------------- permute [B,C,H,W,T] -> [B*T,C,H,W] --------------------
__global__ void permute_kernel(const float* __restrict__ x, float* __restrict__ xt) {
    // block per (b,c,h); 32x64 tile (w x t)
    int bidx = blockIdx.x;
    int h = bidx & 31;
    int c = (bidx >> 5) % 3;
    int b = bidx / 96;
    __shared__ float s[32][65];
    const float* src = x + (size_t)(((b * 3 + c) * 32 + h) * 32) * 64;  // + w*64 + t
    for (int i = threadIdx.x; i < 2048; i += blockDim.x) {
        int w = i >> 6, t = i & 63;
        s[w][t] = src[i];
    }
    __syncthreads();
    for (int i = threadIdx.x; i < 2048; i += blockDim.x) {
        int t = i >> 5, w = i & 31;
        xt[((size_t)((b * 64 + t) * 3 + c) << 10) + (h << 5) + w] = s[w][t];
    }
}

// -------------------- fused conv3x3 (+optional 2x2 maxpool of A, +optional 2x
//                      nearest upsample of A, +optional concat input B, +ReLU)
// inA: CA channels. If POOLA: stored at 2*HS res (pooled into smem).
//                   If UPA:   stored at HS/2 res (indexed as upsample).
// inB: CB channels at HS res (channels CA..CA+CB-1 of the conv input).
template<int CA, int CB, int COUT, int HS, int NBT, int NPIX, bool POOLA, bool UPA>
__global__ void conv3x3_k(const float* __restrict__ inA, const float* __restrict__ inB,
                          const float* __restrict__ wgt, const float* __restrict__ bias,
                          float* __restrict__ out)
{
    constexpr int CIN = CA + CB;
    constexpr int HA  = UPA ? (HS / 2) : HS;   // smem-stored resolution of A
    constexpr int ASZ = CA * HA * HA;
    constexpr int BSZ = CB * HS * HS;
    constexpr int WSZ = COUT * CIN * 9;

    extern __shared__ float sm[];
    float* sW  = sm;                  // WSZ
    float* sBi = sW + WSZ;            // COUT
    float* sIn = sBi + COUT;          // NBT*(ASZ+BSZ)

    const int tid = threadIdx.x;
    const int NT  = blockDim.x;       // == NBT*HS*HS/NPIX
    const int bt0 = blockIdx.x * NBT;

    for (int i = tid; i < WSZ; i += NT) sW[i] = wgt[i];
    for (int i = tid; i < COUT; i += NT) sBi[i] = bias[i];

    // load input A (with pooling if requested)
    for (int i = tid; i < NBT * ASZ; i += NT) {
        int n = i / ASZ, r = i % ASZ;
        int c = r / (HA * HA), p = r % (HA * HA);
        float v;
        if (POOLA) {
            int hh = p / HA, ww = p % HA;
            const float* s = inA + (size_t)((bt0 + n) * CA + c) * (4 * HA * HA)
                                 + (2 * hh) * (2 * HA) + 2 * ww;
            v = fmaxf(fmaxf(s[0], s[1]), fmaxf(s[2 * HA], s[2 * HA + 1]));
        } else {
            v = inA[(size_t)((bt0 + n) * CA + c) * (HA * HA) + p];
        }
        sIn[n * (ASZ + BSZ) + c * (HA * HA) + p] = v;
    }
    if (CB > 0) {
        for (int i = tid; i < NBT * BSZ; i += NT) {
            int n = i / BSZ, r = i % BSZ;
            sIn[n * (ASZ + BSZ) + ASZ + r] = inB[(size_t)(bt0 + n) * BSZ + r];
        }
    }
    __syncthreads();

    // compute: thread handles NPIX consecutive w for all COUT channels
    constexpr int PXT = HS * HS / NPIX;
    const int n  = tid / PXT;
    const int p  = tid % PXT;
    const int h  = p / (HS / NPIX);
    const int w0 = (p % (HS / NPIX)) * NPIX;
    const float* sI = sIn + n * (ASZ + BSZ);

    float acc[COUT][NPIX];
    #pragma unroll
    for (int co = 0; co < COUT; co++) {
        float b = sBi[co];
        #pragma unroll
        for (int j = 0; j < NPIX; j++) acc[co][j] = b;
    }

    #pragma unroll 1
    for (int ci = 0; ci < CIN; ci++) {
        const bool isA = (ci < CA);
        const float* ch = isA ? (sI + ci * HA * HA) : (sI + ASZ + (ci - CA) * HS * HS);
        #pragma unroll
        for (int kh = 0; kh < 3; kh++) {
            int ih = h + kh - 1;
            float v[NPIX + 2];
            #pragma unroll
            for (int j = 0; j < NPIX + 2; j++) {
                int iw = w0 + j - 1;
                bool ok = (ih >= 0) && (ih < HS) && (iw >= 0) && (iw < HS);
                if (!ok) { v[j] = 0.f; }
                else if (isA && UPA) { v[j] = ch[(ih >> 1) * HA + (iw >> 1)]; }
                else { v[j] = ch[ih * HS + iw]; }
            }
            #pragma unroll
            for (int co = 0; co < COUT; co++) {
                const float* wp = sW + ((co * CIN + ci) * 3 + kh) * 3;
                float wa = wp[0], wb = wp[1], wc = wp[2];
                #pragma unroll
                for (int j = 0; j < NPIX; j++)
                    acc[co][j] = fmaf(wa, v[j], fmaf(wb, v[j + 1], fmaf(wc, v[j + 2], acc[co][j])));
            }
        }
    }

    const int btn = bt0 + n;
    #pragma unroll
    for (int co = 0; co < COUT; co++) {
        float* op = out + (size_t)((btn * COUT + co) * HS + h) * HS + w0;
        #pragma unroll
        for (int j = 0; j < NPIX; j++) op[j] = fmaxf(acc[co][j], 0.f);
    }
}

// -------------------- 1x1 conv -> softmax(3ch incl. ones) -> masked feat ----
__global__ void mask_feat_kernel(const float* __restrict__ d1, const float* __restrict__ xt,
                                 const float* __restrict__ ow, const float* __restrict__ ob,
                                 float* __restrict__ feat)
{
    int idx = blockIdx.x * blockDim.x + threadIdx.x;
    if (idx >= BT * 1024) return;
    int bt = idx >> 10, hw = idx & 1023;
    const float* dp = d1 + (size_t)bt * 8 * 1024 + hw;
    float l0 = ob[0], l1 = ob[1];
    #pragma unroll
    for (int c = 0; c < 8; c++) {
        float v = dp[(size_t)c << 10];
        l0 = fmaf(v, ow[c], l0);
        l1 = fmaf(v, ow[8 + c], l1);
    }
    float mx = fmaxf(fmaxf(l0, l1), 1.0f);
    float e0 = expf(l0 - mx), e1 = expf(l1 - mx), e2 = expf(1.0f - mx);
    float inv = 1.0f / (e0 + e1 + e2);
    float m0 = e0 * inv, m1 = e1 * inv;

    const float* xp = xt + (size_t)bt * 3 * 1024 + hw;
    float* fp = feat + (size_t)bt * FEAT + hw;
    #pragma unroll
    for (int c = 0; c < 3; c++) {
        float xv = xp[(size_t)c << 10];
        fp[(size_t)c << 10]       = m0 * xv;
        fp[(size_t)(3 + c) << 10] = m1 * xv;
    }
}

// -------------------- tiled SGEMM: C[M,N] = relu(A[M,K] @ B[K,N] + bias) -----
template<int BM, int BN, int BK, int TM, int TN, bool RELU>
__global__ void sgemm_k(int M, int N, int K,
                        const float* __restrict__ A, const float* __restrict__ Bm,
                        const float* __restrict__ bias, float* __restrict__ C)
{
    __shared__ float sA[BK][BM + 1];
    __shared__ float sB[BK][BN];
    const int tid = threadIdx.x;                 // 256 threads
    const int tx = tid % (BN / TN);
    const int ty = tid / (BN / TN);
    const int bm = blockIdx.y * BM;
    const int bn = blockIdx.x * BN;

    float acc[TM][TN];
    #pragma unroll
    for (int i = 0; i < TM; i++)
        #pragma unroll
        for (int j = 0; j < TN; j++) acc[i][j] = 0.f;

    for (int k0 = 0; k0 < K; k0 += BK) {
        for (int i = tid; i < BM * BK; i += 256) {
            int m = i / BK, kk = i % BK;
            sA[kk][m] = (bm + m < M && k0 + kk < K) ? A[(size_t)(bm + m) * K + k0 + kk] : 0.f;
        }
        for (int i = tid; i < BK * BN; i += 256) {
            int kk = i / BN, n = i % BN;
            sB[kk][n] = (k0 + kk < K && bn + n < N) ? Bm[(size_t)(k0 + kk) * N + bn + n] : 0.f;
        }
        __syncthreads();
        #pragma unroll
        for (int kk = 0; kk < BK; kk++) {
            float a[TM], b[TN];
            #pragma unroll
            for (int i = 0; i < TM; i++) a[i] = sA[kk][ty * TM + i];
            #pragma unroll
            for (int j = 0; j < TN; j++) b[j] = sB[kk][tx * TN + j];
            #pragma unroll
            for (int i = 0; i < TM; i++)
                #pragma unroll
                for (int j = 0; j < TN; j++) acc[i][j] = fmaf(a[i], b[j], acc[i][j]);
        }
        __syncthreads();
    }

    #pragma unroll
    for (int i = 0; i < TM; i++) {
        int m = bm + ty * TM + i;
        if (m >= M) continue;
        #pragma unroll
        for (int j = 0; j < TN; j++) {
            int n = bn + tx * TN + j;
            if (n >= N) continue;
            float v = acc[i][j] + bias[n];
            if (RELU) v = fmaxf(v, 0.f);
            C[(size_t)m * N + n] = v;
        }
    }
}

// -------------------- final 200->4 + tanh scale ------------------------------
__global__ void loc3_kernel(const float* __restrict__ h2, const float* __restrict__ w3,
                            const float* __restrict__ b3, float* __restrict__ out)
{
    int idx = blockIdx.x * blockDim.x + threadIdx.x;
    if (idx >= BT * 4) return;
    int m = idx >> 2, j = idx & 3;
    float acc = b3[j];
    const float* hp = h2 + (size_t)m * HID;
    #pragma unroll 8
    for (int k = 0; k < HID; k++) acc = fmaf(hp[k], w3[k * 4 + j], acc);
    out[idx] = tanhf(acc) * 16.f + 16.f;
}

// -------------------- launch --------------------------------------------------
extern "C" void kernel_launch(void* const* d_in, const int* in_sizes, int n_in,
                              void* d_out, int out_size)
{
    const float* x   = (const float*)d_in[0];
    const float* ew1 = (const float*)d_in[1];
    const float* eb1 = (const float*)d_in[2];
    const float* ew2 = (const float*)d_in[3];
    const float* eb2 = (const float*)d_in[4];
    const float* ew3 = (const float*)d_in[5];
    const float* eb3 = (const float*)d_in[6];
    const float* dw2 = (const float*)d_in[7];
    const float* db2 = (const float*)d_in[8];
    const float* dw1 = (const float*)d_in[9];
    const float* db1 = (const float*)d_in[10];
    const float* ow  = (const float*)d_in[11];
    const float* ob  = (const float*)d_in[12];
    const float* lw1 = (const float*)d_in[13];
    const float* lb1 = (const float*)d_in[14];
    const float* lw2 = (const float*)d_in[15];
    const float* lb2 = (const float*)d_in[16];
    const float* lw3 = (const float*)d_in[17];
    const float* lb3 = (const float*)d_in[18];
    float* out = (float*)d_out;

    float *xt, *e1, *e2, *e3, *d2v, *d1v, *feat, *h1, *h2;
    cudaGetSymbolAddress((void**)&xt,   g_xt);
    cudaGetSymbolAddress((void**)&e1,   g_e1);
    cudaGetSymbolAddress((void**)&e2,   g_e2);
    cudaGetSymbolAddress((void**)&e3,   g_e3);
    cudaGetSymbolAddress((void**)&d2v,  g_d2);
    cudaGetSymbolAddress((void**)&d1v,  g_d1);
    cudaGetSymbolAddress((void**)&feat, g_feat);
    cudaGetSymbolAddress((void**)&h1,   g_h1);
    cudaGetSymbolAddress((void**)&h2,   g_h2);

    // smem sizes (floats -> bytes)
    constexpr int SM1 = (3  * 8  * 9 + 8  + 2  * 3  * 1024) * 4;                 // 25472
    constexpr int SM2 = (8  * 16 * 9 + 16 + 4  * 8  * 256) * 4;                  // 37440
    constexpr int SM3 = (16 * 32 * 9 + 32 + 16 * 16 * 64) * 4;                   // 84096
    constexpr int SM4 = (48 * 16 * 9 + 16 + 4 * (32 * 64 + 16 * 256)) * 4;       // 126016
    constexpr int SM5 = (24 * 8  * 9 + 8  + 2 * (16 * 256 + 8 * 1024)) * 4;      // 105248

    cudaFuncSetAttribute((const void*)conv3x3_k<16, 0, 32, 8, 16, 2, true, false>,
                         cudaFuncAttributeMaxDynamicSharedMemorySize, SM3);
    cudaFuncSetAttribute((const void*)conv3x3_k<32, 16, 16, 16, 4, 4, false, true>,
                         cudaFuncAttributeMaxDynamicSharedMemorySize, SM4);
    cudaFuncSetAttribute((const void*)conv3x3_k<16, 8, 8, 32, 2, 4, false, true>,
                         cudaFuncAttributeMaxDynamicSharedMemorySize, SM5);

    // 1) permute
    permute_kernel<<<32 * 3 * 32, 256>>>(x, xt);
    // 2) e1 = relu(conv 3->8 @32)
    conv3x3_k<3, 0, 8, 32, 2, 4, false, false><<<BT / 2, 512, SM1>>>(xt, nullptr, ew1, eb1, e1);
    // 3) e2 = relu(conv pool(e1) 8->16 @16)
    conv3x3_k<8, 0, 16, 16, 4, 4, true, false><<<BT / 4, 256, SM2>>>(e1, nullptr, ew2, eb2, e2);
    // 4) e3 = relu(conv pool(e2) 16->32 @8)
    conv3x3_k<16, 0, 32, 8, 16, 2, true, false><<<BT / 16, 512, SM3>>>(e2, nullptr, ew3, eb3, e3);
    // 5) d2 = relu(conv [up(e3), e2] 48->16 @16)
    conv3x3_k<32, 16, 16, 16, 4, 4, false, true><<<BT / 4, 256, SM4>>>(e3, e2, dw2, db2, d2v);
    // 6) d1 = relu(conv [up(d2), e1] 24->8 @32)
    conv3x3_k<16, 8, 8, 32, 2, 4, false, true><<<BT / 2, 512, SM5>>>(d2v, e1, dw1, db1, d1v);
    // 7) masks + masked features
    mask_feat_kernel<<<(BT * 1024) / 256, 256>>>(d1v, xt, ow, ob, feat);
    // 8) h1 = relu(feat @ lw1 + lb1)   [2048,6144]x[6144,200]
    sgemm_k<64, 64, 16, 4, 4, true><<<dim3((HID + 63) / 64, BT / 64), 256>>>(BT, HID, FEAT, feat, lw1, lb1, h1);
    // 9) h2 = relu(h1 @ lw2 + lb2)     [2048,200]x[200,200]
    sgemm_k<64, 64, 16, 4, 4, true><<<dim3((HID + 63) / 64, BT / 64), 256>>>(BT, HID, HID, h1, lw2, lb2, h2);
    // 10) out = tanh(h2 @ lw3 + lb3)*16+16
    loc3_kernel<<<(BT * 4 + 255) / 256, 256>>>(h2, lw3, lb3, out);
}

// round 2
// speedup vs baseline: 2.0342x; 2.0342x over previous
#include <cuda_runtime.h>
#include <cuda_bf16.h>
#include <math.h>

#define BB 32
#define TT 64
#define BT 2048
#define HID 200
#define FEAT 6144

// -------------------- scratch (device globals; no allocs) --------------------
__device__ float g_xt  [BT * 3  * 1024];
__device__ float g_e1  [BT * 8  * 1024];
__device__ float g_e2  [BT * 16 * 256];
__device__ float g_e3  [BT * 32 * 64];
__device__ float g_d2  [BT * 16 * 256];
__device__ float g_d1  [BT * 8  * 1024];
__device__ float g_feat[BT * FEAT];
__device__ float g_h1  [BT * HID];
__device__ float g_h2  [BT * HID];
__device__ float g_part[4 * BT * HID];   // split-K partials

// -------------------- permute [B,C,H,W,T] -> [B*T,C,H,W] --------------------
__global__ void permute_kernel(const float* __restrict__ x, float* __restrict__ xt) {
    int bidx = blockIdx.x;
    int h = bidx & 31;
    int c = (bidx >> 5) % 3;
    int b = bidx / 96;
    __shared__ float s[32][65];
    const float* src = x + (size_t)(((b * 3 + c) * 32 + h) * 32) * 64;
    for (int i = threadIdx.x; i < 2048; i += blockDim.x) {
        int w = i >> 6, t = i & 63;
        s[w][t] = src[i];
    }
    __syncthreads();
    for (int i = threadIdx.x; i < 2048; i += blockDim.x) {
        int t = i >> 5, w = i & 31;
        xt[((size_t)((b * 64 + t) * 3 + c) << 10) + (h << 5) + w] = s[w][t];
    }
}

// -------------------- standard conv3x3 (+optional 2x2 maxpool of input, +ReLU)
// each thread: COUT_T output channels x NPIX consecutive w pixels
template<int CA, int COUT, int COUT_T, int HS, int NBT, int NPIX, bool POOL>
__global__ void __launch_bounds__(256, 2)
conv_std_k(const float* __restrict__ inA, const float* __restrict__ wgt,
           const float* __restrict__ bias, float* __restrict__ out)
{
    constexpr int GP  = COUT / COUT_T;
    constexpr int PXT = HS * HS / NPIX;
    constexpr int ASZ = CA * HS * HS;
    constexpr int WSZ = COUT * CA * 9;
    extern __shared__ float sm[];
    float* sW  = sm;
    float* sBi = sW + WSZ;
    float* sIn = sBi + COUT;

    const int tid = threadIdx.x, NT = blockDim.x;
    const int bt0 = blockIdx.x * NBT;

    for (int i = tid; i < WSZ; i += NT) sW[i] = wgt[i];
    for (int i = tid; i < COUT; i += NT) sBi[i] = bias[i];
    for (int i = tid; i < NBT * ASZ; i += NT) {
        int nn = i / ASZ, rr = i % ASZ;
        float v;
        if (POOL) {
            int c = rr / (HS * HS), pp = rr % (HS * HS);
            int hh = pp / HS, ww = pp % HS;
            const float* s = inA + (size_t)((bt0 + nn) * CA + c) * (4 * HS * HS)
                                 + (2 * hh) * (2 * HS) + 2 * ww;
            v = fmaxf(fmaxf(s[0], s[1]), fmaxf(s[2 * HS], s[2 * HS + 1]));
        } else {
            v = inA[(size_t)(bt0 + nn) * ASZ + rr];
        }
        sIn[nn * ASZ + rr] = v;
    }
    __syncthreads();

    const int n   = tid / (GP * PXT);
    const int r   = tid % (GP * PXT);
    const int cog = r / PXT;
    const int p   = r % PXT;
    const int h   = p / (HS / NPIX);
    const int w0  = (p % (HS / NPIX)) * NPIX;
    const float* sI = sIn + n * ASZ;

    float acc[COUT_T][NPIX];
    #pragma unroll
    for (int co = 0; co < COUT_T; co++) {
        float b = sBi[cog * COUT_T + co];
        #pragma unroll
        for (int j = 0; j < NPIX; j++) acc[co][j] = b;
    }

    #pragma unroll 1
    for (int ci = 0; ci < CA; ci++) {
        const float* ch = sI + ci * HS * HS;
        #pragma unroll
        for (int kh = 0; kh < 3; kh++) {
            int ih = h + kh - 1;
            bool rowok = (ih >= 0) && (ih < HS);
            float v[NPIX + 2];
            #pragma unroll
            for (int j = 0; j < NPIX + 2; j++) {
                int iw = w0 + j - 1;
                v[j] = (rowok && iw >= 0 && iw < HS) ? ch[ih * HS + iw] : 0.f;
            }
            #pragma unroll
            for (int co = 0; co < COUT_T; co++) {
                const float* wp = sW + (((cog * COUT_T + co) * CA + ci) * 3 + kh) * 3;
                float wa = wp[0], wb = wp[1], wc = wp[2];
                #pragma unroll
                for (int j = 0; j < NPIX; j++)
                    acc[co][j] = fmaf(wa, v[j], fmaf(wb, v[j + 1], fmaf(wc, v[j + 2], acc[co][j])));
            }
        }
    }

    const int btn = bt0 + n;
    #pragma unroll
    for (int co = 0; co < COUT_T; co++) {
        float* op = out + (size_t)((btn * COUT + cog * COUT_T + co) * HS + h) * HS + w0;
        #pragma unroll
        for (int j = 0; j < NPIX; j += 4)
            *reinterpret_cast<float4*>(op + j) =
                make_float4(fmaxf(acc[co][j], 0.f), fmaxf(acc[co][j + 1], 0.f),
                            fmaxf(acc[co][j + 2], 0.f), fmaxf(acc[co][j + 3], 0.f));
    }
}

// -------------------- decoder conv3x3 over [up2x(A), B] + ReLU ---------------
// A is kept at coarse resolution HA=HS/2; the 3x3 over nearest-upsampled A
// collapses to a 2x2 coarse stencil with parity-folded weights (4 MACs/cin).
template<int CA, int CB, int COUT, int COUT_T, int HS, int NBT, int NPIX>
__global__ void __launch_bounds__(256, 2)
conv_up_k(const float* __restrict__ inA, const float* __restrict__ inB,
          const float* __restrict__ wgt, const float* __restrict__ bias,
          float* __restrict__ out)
{
    constexpr int CIN = CA + CB;
    constexpr int HA  = HS / 2;
    constexpr int ASZ = CA * HA * HA;
    constexpr int BSZ = CB * HS * HS;
    constexpr int GP  = COUT / COUT_T;
    constexpr int PXT = HS * HS / NPIX;
    constexpr int WSZ = COUT * CIN * 9;
    constexpr int NC  = NPIX / 2 + 2;   // coarse cols needed per row

    extern __shared__ float sm[];
    float* sW  = sm;
    float* sBi = sW + WSZ;
    float* sIn = sBi + COUT;

    const int tid = threadIdx.x, NT = blockDim.x;
    const int bt0 = blockIdx.x * NBT;

    for (int i = tid; i < WSZ; i += NT) sW[i] = wgt[i];
    for (int i = tid; i < COUT; i += NT) sBi[i] = bias[i];
    for (int i = tid; i < NBT * ASZ; i += NT) {
        int nn = i / ASZ, rr = i % ASZ;
        sIn[nn * (ASZ + BSZ) + rr] = inA[(size_t)(bt0 + nn) * ASZ + rr];
    }
    for (int i = tid; i < NBT * BSZ; i += NT) {
        int nn = i / BSZ, rr = i % BSZ;
        sIn[nn * (ASZ + BSZ) + ASZ + rr] = inB[(size_t)(bt0 + nn) * BSZ + rr];
    }
    __syncthreads();

    const int n   = tid / (GP * PXT);
    const int r   = tid % (GP * PXT);
    const int cog = r / PXT;
    const int p   = r % PXT;
    const int h   = p / (HS / NPIX);
    const int w0  = (p % (HS / NPIX)) * NPIX;
    const float* sI = sIn + n * (ASZ + BSZ);

    float acc[COUT_T][NPIX];
    #pragma unroll
    for (int co = 0; co < COUT_T; co++) {
        float b = sBi[cog * COUT_T + co];
        #pragma unroll
        for (int j = 0; j < NPIX; j++) acc[co][j] = b;
    }

    // ---- A part: coarse 2x2 stencil with parity-folded weights ----
    const int  a    = h >> 1;
    const bool hodd = (h & 1) != 0;
    const int  rowA = hodd ? a : a - 1;       // always < HA
    const int  rowB = hodd ? a + 1 : a;       // always >= 0
    const int  cs0  = (w0 >> 1) - 1;

    #pragma unroll 1
    for (int ci = 0; ci < CA; ci++) {
        const float* ch = sI + ci * HA * HA;
        float cAr[NC], cBr[NC];
        #pragma unroll
        for (int k = 0; k < NC; k++) {
            int cc = cs0 + k;
            bool cok = (cc >= 0) && (cc < HA);
            cAr[k] = (cok && rowA >= 0) ? ch[rowA * HA + cc] : 0.f;
            cBr[k] = (cok && rowB < HA) ? ch[rowB * HA + cc] : 0.f;
        }
        #pragma unroll
        for (int co = 0; co < COUT_T; co++) {
            const float* wp = sW + ((cog * COUT_T + co) * CIN + ci) * 9;
            float w00 = wp[0], w01 = wp[1], w02 = wp[2];
            float w10 = wp[3], w11 = wp[4], w12 = wp[5];
            float w20 = wp[6], w21 = wp[7], w22 = wp[8];
            // vertical fold by h parity
            float rA0 = hodd ? (w00 + w10) : w00;
            float rA1 = hodd ? (w01 + w11) : w01;
            float rA2 = hodd ? (w02 + w12) : w02;
            float rB0 = hodd ? w20 : (w10 + w20);
            float rB1 = hodd ? w21 : (w11 + w21);
            float rB2 = hodd ? w22 : (w12 + w22);
            // horizontal fold variants
            float sA0 = rA0, sA01 = rA0 + rA1, sA12 = rA1 + rA2, sA2 = rA2;
            float sB0 = rB0, sB01 = rB0 + rB1, sB12 = rB1 + rB2, sB2 = rB2;
            #pragma unroll
            for (int j = 0; j < NPIX; j++) {
                int lb = (j >> 1) + 1;
                if ((j & 1) == 0) {
                    acc[co][j] = fmaf(cAr[lb - 1], sA0,  acc[co][j]);
                    acc[co][j] = fmaf(cAr[lb],     sA12, acc[co][j]);
                    acc[co][j] = fmaf(cBr[lb - 1], sB0,  acc[co][j]);
                    acc[co][j] = fmaf(cBr[lb],     sB12, acc[co][j]);
                } else {
                    acc[co][j] = fmaf(cAr[lb],     sA01, acc[co][j]);
                    acc[co][j] = fmaf(cAr[lb + 1], sA2,  acc[co][j]);
                    acc[co][j] = fmaf(cBr[lb],     sB01, acc[co][j]);
                    acc[co][j] = fmaf(cBr[lb + 1], sB2,  acc[co][j]);
                }
            }
        }
    }

    // ---- B part: standard fine 3x3 ----
    #pragma unroll 1
    for (int ci = 0; ci < CB; ci++) {
        const float* ch = sI + ASZ + ci * HS * HS;
        #pragma unroll
        for (int kh = 0; kh < 3; kh++) {
            int ih = h + kh - 1;
            bool rowok = (ih >= 0) && (ih < HS);
            float v[NPIX + 2];
            #pragma unroll
            for (int j = 0; j < NPIX + 2; j++) {
                int iw = w0 + j - 1;
                v[j] = (rowok && iw >= 0 && iw < HS) ? ch[ih * HS + iw] : 0.f;
            }
            #pragma unroll
            for (int co = 0; co < COUT_T; co++) {
                const float* wp = sW + (((cog * COUT_T + co) * CIN + CA + ci) * 3 + kh) * 3;
                float wa = wp[0], wb = wp[1], wc = wp[2];
                #pragma unroll
                for (int j = 0; j < NPIX; j++)
                    acc[co][j] = fmaf(wa, v[j], fmaf(wb, v[j + 1], fmaf(wc, v[j + 2], acc[co][j])));
            }
        }
    }

    const int btn = bt0 + n;
    #pragma unroll
    for (int co = 0; co < COUT_T; co++) {
        float* op = out + (size_t)((btn * COUT + cog * COUT_T + co) * HS + h) * HS + w0;
        #pragma unroll
        for (int j = 0; j < NPIX; j += 4)
            *reinterpret_cast<float4*>(op + j) =
                make_float4(fmaxf(acc[co][j], 0.f), fmaxf(acc[co][j + 1], 0.f),
                            fmaxf(acc[co][j + 2], 0.f), fmaxf(acc[co][j + 3], 0.f));
    }
}

// -------------------- 1x1 conv -> softmax(3ch incl. ones) -> masked feat ----
__global__ void mask_feat_kernel(const float* __restrict__ d1, const float* __restrict__ xt,
                                 const float* __restrict__ ow, const float* __restrict__ ob,
                                 float* __restrict__ feat)
{
    int idx = blockIdx.x * blockDim.x + threadIdx.x;
    if (idx >= BT * 1024) return;
    int bt = idx >> 10, hw = idx & 1023;
    const float* dp = d1 + (size_t)bt * 8 * 1024 + hw;
    float l0 = ob[0], l1 = ob[1];
    #pragma unroll
    for (int c = 0; c < 8; c++) {
        float v = dp[(size_t)c << 10];
        l0 = fmaf(v, ow[c], l0);
        l1 = fmaf(v, ow[8 + c], l1);
    }
    float mx = fmaxf(fmaxf(l0, l1), 1.0f);
    float e0 = expf(l0 - mx), e1 = expf(l1 - mx), e2 = expf(1.0f - mx);
    float inv = 1.0f / (e0 + e1 + e2);
    float m0 = e0 * inv, m1 = e1 * inv;

    const float* xp = xt + (size_t)bt * 3 * 1024 + hw;
    float* fp = feat + (size_t)bt * FEAT + hw;
    #pragma unroll
    for (int c = 0; c < 3; c++) {
        float xv = xp[(size_t)c << 10];
        fp[(size_t)c << 10]       = m0 * xv;
        fp[(size_t)(3 + c) << 10] = m1 * xv;
    }
}

// -------------------- tiled SGEMM (full-K, bias+relu) -------------------------
template<int BM, int BN, int BK, int TM, int TN, bool RELU>
__global__ void sgemm_k(int M, int N, int K,
                        const float* __restrict__ A, const float* __restrict__ Bm,
                        const float* __restrict__ bias, float* __restrict__ C)
{
    __shared__ float sA[BK][BM + 1];
    __shared__ float sB[BK][BN];
    const int tid = threadIdx.x;
    const int tx = tid % (BN / TN);
    const int ty = tid / (BN / TN);
    const int bm = blockIdx.y * BM;
    const int bn = blockIdx.x * BN;

    float acc[TM][TN];
    #pragma unroll
    for (int i = 0; i < TM; i++)
        #pragma unroll
        for (int j = 0; j < TN; j++) acc[i][j] = 0.f;

    for (int k0 = 0; k0 < K; k0 += BK) {
        for (int i = tid; i < BM * BK; i += 256) {
            int m = i / BK, kk = i % BK;
            sA[kk][m] = (bm + m < M && k0 + kk < K) ? A[(size_t)(bm + m) * K + k0 + kk] : 0.f;
        }
        for (int i = tid; i < BK * BN; i += 256) {
            int kk = i / BN, n = i % BN;
            sB[kk][n] = (k0 + kk < K && bn + n < N) ? Bm[(size_t)(k0 + kk) * N + bn + n] : 0.f;
        }
        __syncthreads();
        #pragma unroll
        for (int kk = 0; kk < BK; kk++) {
            float a[TM], b[TN];
            #pragma unroll
            for (int i = 0; i < TM; i++) a[i] = sA[kk][ty * TM + i];
            #pragma unroll
            for (int j = 0; j < TN; j++) b[j] = sB[kk][tx * TN + j];
            #pragma unroll
            for (int i = 0; i < TM; i++)
                #pragma unroll
                for (int j = 0; j < TN; j++) acc[i][j] = fmaf(a[i], b[j], acc[i][j]);
        }
        __syncthreads();
    }

    #pragma unroll
    for (int i = 0; i < TM; i++) {
        int m = bm + ty * TM + i;
        if (m >= M) continue;
        #pragma unroll
        for (int j = 0; j < TN; j++) {
            int n = bn + tx * TN + j;
            if (n >= N) continue;
            float v = acc[i][j] + bias[n];
            if (RELU) v = fmaxf(v, 0.f);
            C[(size_t)m * N + n] = v;
        }
    }
}

// -------------------- split-K SGEMM: partial C per blockIdx.z ----------------
template<int BM, int BN, int BK, int TM, int TN>
__global__ void sgemm_split_k(int M, int N, int K, int KS,
                              const float* __restrict__ A, const float* __restrict__ Bm,
                              float* __restrict__ Cpart)
{
    __shared__ float sA[BK][BM + 1];
    __shared__ float sB[BK][BN];
    const int tid = threadIdx.x;
    const int tx = tid % (BN / TN);
    const int ty = tid / (BN / TN);
    const int bm = blockIdx.y * BM;
    const int bn = blockIdx.x * BN;
    const int kbase = blockIdx.z * KS;

    float acc[TM][TN];
    #pragma unroll
    for (int i = 0; i < TM; i++)
        #pragma unroll
        for (int j = 0; j < TN; j++) acc[i][j] = 0.f;

    for (int k0 = kbase; k0 < kbase + KS; k0 += BK) {
        for (int i = tid; i < BM * BK; i += 256) {
            int m = i / BK, kk = i % BK;
            sA[kk][m] = (bm + m < M) ? A[(size_t)(bm + m) * K + k0 + kk] : 0.f;
        }
        for (int i = tid; i < BK * BN; i += 256) {
            int kk = i / BN, n = i % BN;
            sB[kk][n] = (bn + n < N) ? Bm[(size_t)(k0 + kk) * N + bn + n] : 0.f;
        }
        __syncthreads();
        #pragma unroll
        for (int kk = 0; kk < BK; kk++) {
            float a[TM], b[TN];
            #pragma unroll
            for (int i = 0; i < TM; i++) a[i] = sA[kk][ty * TM + i];
            #pragma unroll
            for (int j = 0; j < TN; j++) b[j] = sB[kk][tx * TN + j];
            #pragma unroll
            for (int i = 0; i < TM; i++)
                #pragma unroll
                for (int j = 0; j < TN; j++) acc[i][j] = fmaf(a[i], b[j], acc[i][j]);
        }
        __syncthreads();
    }

    float* Cp = Cpart + (size_t)blockIdx.z * M * N;
    #pragma unroll
    for (int i = 0; i < TM; i++) {
        int m = bm + ty * TM + i;
        if (m >= M) continue;
        #pragma unroll
        for (int j = 0; j < TN; j++) {
            int n = bn + tx * TN + j;
            if (n >= N) continue;
            Cp[(size_t)m * N + n] = acc[i][j];
        }
    }
}

__global__ void reduce4_relu_kernel(const float* __restrict__ part,
                                    const float* __restrict__ bias,
                                    float* __restrict__ out)
{
    int idx = blockIdx.x * blockDim.x + threadIdx.x;
    if (idx >= BT * HID) return;
    int n = idx % HID;
    float v = bias[n] + part[idx] + part[BT * HID + idx]
            + part[2 * BT * HID + idx] + part[3 * BT * HID + idx];
    out[idx] = fmaxf(v, 0.f);
}

// -------------------- final 200->4 + tanh scale ------------------------------
__global__ void loc3_kernel(const float* __restrict__ h2, const float* __restrict__ w3,
                            const float* __restrict__ b3, float* __restrict__ out)
{
    int idx = blockIdx.x * blockDim.x + threadIdx.x;
    if (idx >= BT * 4) return;
    int m = idx >> 2, j = idx & 3;
    float acc = b3[j];
    const float* hp = h2 + (size_t)m * HID;
    #pragma unroll 8
    for (int k = 0; k < HID; k++) acc = fmaf(hp[k], w3[k * 4 + j], acc);
    out[idx] = tanhf(acc) * 16.f + 16.f;
}

// -------------------- launch --------------------------------------------------
extern "C" void kernel_launch(void* const* d_in, const int* in_sizes, int n_in,
                              void* d_out, int out_size)
{
    const float* x   = (const float*)d_in[0];
    const float* ew1 = (const float*)d_in[1];
    const float* eb1 = (const float*)d_in[2];
    const float* ew2 = (const float*)d_in[3];
    const float* eb2 = (const float*)d_in[4];
    const float* ew3 = (const float*)d_in[5];
    const float* eb3 = (const float*)d_in[6];
    const float* dw2 = (const float*)d_in[7];
    const float* db2 = (const float*)d_in[8];
    const float* dw1 = (const float*)d_in[9];
    const float* db1 = (const float*)d_in[10];
    const float* ow  = (const float*)d_in[11];
    const float* ob  = (const float*)d_in[12];
    const float* lw1 = (const float*)d_in[13];
    const float* lb1 = (const float*)d_in[14];
    const float* lw2 = (const float*)d_in[15];
    const float* lb2 = (const float*)d_in[16];
    const float* lw3 = (const float*)d_in[17];
    const float* lb3 = (const float*)d_in[18];
    float* out = (float*)d_out;

    float *xt, *e1, *e2, *e3, *d2v, *d1v, *feat, *h1, *h2, *part;
    cudaGetSymbolAddress((void**)&xt,   g_xt);
    cudaGetSymbolAddress((void**)&e1,   g_e1);
    cudaGetSymbolAddress((void**)&e2,   g_e2);
    cudaGetSymbolAddress((void**)&e3,   g_e3);
    cudaGetSymbolAddress((void**)&d2v,  g_d2);
    cudaGetSymbolAddress((void**)&d1v,  g_d1);
    cudaGetSymbolAddress((void**)&feat, g_feat);
    cudaGetSymbolAddress((void**)&h1,   g_h1);
    cudaGetSymbolAddress((void**)&h2,   g_h2);
    cudaGetSymbolAddress((void**)&part, g_part);

    // smem bytes
    constexpr int SM_E1 = (3  * 8  * 9 + 8  + 2 * 3  * 1024) * 4;               // 25472
    constexpr int SM_E2 = (8  * 16 * 9 + 16 + 4 * 8  * 256) * 4;                // 37440
    constexpr int SM_E3 = (16 * 32 * 9 + 32 + 8 * 16 * 64) * 4;                 // 51328
    constexpr int SM_D2 = (48 * 16 * 9 + 16 + 2 * (32 * 64 + 16 * 256)) * 4;    // 76864
    constexpr int SM_D1 = (24 * 8  * 9 + 8  + 2 * (16 * 256 + 8 * 1024)) * 4;   // 105248

    cudaFuncSetAttribute((const void*)conv_std_k<16, 32, 8, 8, 8, 8, true>,
                         cudaFuncAttributeMaxDynamicSharedMemorySize, SM_E3);
    cudaFuncSetAttribute((const void*)conv_up_k<32, 16, 16, 4, 16, 2, 8>,
                         cudaFuncAttributeMaxDynamicSharedMemorySize, SM_D2);
    cudaFuncSetAttribute((const void*)conv_up_k<16, 8, 8, 8, 32, 2, 8>,
                         cudaFuncAttributeMaxDynamicSharedMemorySize, SM_D1);

    // 1) permute
    permute_kernel<<<32 * 3 * 32, 256>>>(x, xt);
    // 2) e1 = relu(conv 3->8 @32)
    conv_std_k<3, 8, 8, 32, 2, 8, false><<<BT / 2, 256, SM_E1>>>(xt, ew1, eb1, e1);
    // 3) e2 = relu(conv pool(e1) 8->16 @16)
    conv_std_k<8, 16, 8, 16, 4, 8, true><<<BT / 4, 256, SM_E2>>>(e1, ew2, eb2, e2);
    // 4) e3 = relu(conv pool(e2) 16->32 @8)
    conv_std_k<16, 32, 8, 8, 8, 8, true><<<BT / 8, 256, SM_E3>>>(e2, ew3, eb3, e3);
    // 5) d2 = relu(conv [up(e3), e2] 48->16 @16) — coarse-stencil A-part
    conv_up_k<32, 16, 16, 4, 16, 2, 8><<<BT / 2, 256, SM_D2>>>(e3, e2, dw2, db2, d2v);
    // 6) d1 = relu(conv [up(d2), e1] 24->8 @32) — coarse-stencil A-part
    conv_up_k<16, 8, 8, 8, 32, 2, 8><<<BT / 2, 256, SM_D1>>>(d2v, e1, dw1, db1, d1v);
    // 7) masks + masked features
    mask_feat_kernel<<<(BT * 1024) / 256, 256>>>(d1v, xt, ow, ob, feat);
    // 8) h1 = relu(feat @ lw1 + lb1) via split-K x4
    sgemm_split_k<64, 64, 16, 4, 4><<<dim3(4, BT / 64, 4), 256>>>(BT, HID, FEAT, FEAT / 4, feat, lw1, part);
    reduce4_relu_kernel<<<(BT * HID + 255) / 256, 256>>>(part, lb1, h1);
    // 9) h2 = relu(h1 @ lw2 + lb2)
    sgemm_k<64, 64, 16, 4, 4, true><<<dim3(4, BT / 64), 256>>>(BT, HID, HID, h1, lw2, lb2, h2);
    // 10) out = tanh(h2 @ lw3 + lb3)*16+16
    loc3_kernel<<<(BT * 4 + 255) / 256, 256>>>(h2, lw3, lb3, out);
}

// round 3
// speedup vs baseline: 2.2816x; 1.1216x over previous
#include <cuda_runtime.h>
#include <cuda_bf16.h>
#include <math.h>

#define BB 32
#define TT 64
#define BT 2048
#define HID 200
#define FEAT 6144

// -------------------- scratch (device globals; no allocs) --------------------
__device__ float g_xt  [BT * 3  * 1024];
__device__ float g_e1  [BT * 8  * 1024];
__device__ float g_e2  [BT * 16 * 256];
__device__ float g_e3  [BT * 32 * 64];
__device__ float g_d2  [BT * 16 * 256];
__device__ float g_d1  [BT * 8  * 1024];
__device__ float g_feat[BT * FEAT];
__device__ float g_h1  [BT * HID];
__device__ float g_h2  [BT * HID];
__device__ float g_part[4 * BT * HID];   // split-K partials

// -------------------- permute [B,C,H,W,T] -> [B*T,C,H,W] --------------------
__global__ void permute_kernel(const float* __restrict__ x, float* __restrict__ xt) {
    int bidx = blockIdx.x;
    int h = bidx & 31;
    int c = (bidx >> 5) % 3;
    int b = bidx / 96;
    __shared__ float s[32][65];
    const float* src = x + (size_t)(((b * 3 + c) * 32 + h) * 32) * 64;
    for (int i = threadIdx.x; i < 2048; i += blockDim.x) {
        int w = i >> 6, t = i & 63;
        s[w][t] = src[i];
    }
    __syncthreads();
    for (int i = threadIdx.x; i < 2048; i += blockDim.x) {
        int t = i >> 5, w = i & 31;
        xt[((size_t)((b * 64 + t) * 3 + c) << 10) + (h << 5) + w] = s[w][t];
    }
}

// -------------------- standard conv3x3 (+optional 2x2 maxpool of input, +ReLU)
// SMEM: input rows padded to HS+1 (bank-conflict-free h-strided loads);
//       weights transposed to [ci][kh][kw][co] (conflict-free/broadcast).
template<int CA, int COUT, int COUT_T, int HS, int NBT, int NPIX, bool POOL>
__global__ void __launch_bounds__(256, 2)
conv_std_k(const float* __restrict__ inA, const float* __restrict__ wgt,
           const float* __restrict__ bias, float* __restrict__ out)
{
    constexpr int GP   = COUT / COUT_T;
    constexpr int PXT  = HS * HS / NPIX;
    constexpr int HP   = HS + 1;                 // padded row pitch
    constexpr int CSZ  = HS * HP;                // padded channel size
    constexpr int ASZP = CA * CSZ;
    constexpr int WSZ  = COUT * CA * 9;
    extern __shared__ float sm[];
    float* sW  = sm;                  // transposed weights [CA*9][COUT]
    float* sBi = sW + WSZ;
    float* sIn = sBi + COUT;

    const int tid = threadIdx.x, NT = blockDim.x;
    const int bt0 = blockIdx.x * NBT;

    // weights transposed: sW[(ci*9 + kh*3 + kw)*COUT + co]
    for (int i = tid; i < WSZ; i += NT) {
        int co = i % COUT;
        int rest = i / COUT;          // ci*9 + kh*3 + kw
        int ci = rest / 9, kk = rest % 9;
        sW[i] = wgt[(co * CA + ci) * 9 + kk];
    }
    for (int i = tid; i < COUT; i += NT) sBi[i] = bias[i];

    for (int i = tid; i < NBT * CA * HS * HS; i += NT) {
        int nn = i / (CA * HS * HS), rr = i % (CA * HS * HS);
        int c = rr / (HS * HS), pp = rr % (HS * HS);
        int hh = pp / HS, ww = pp % HS;
        float v;
        if (POOL) {
            const float* s = inA + (size_t)((bt0 + nn) * CA + c) * (4 * HS * HS)
                                 + (2 * hh) * (2 * HS) + 2 * ww;
            v = fmaxf(fmaxf(s[0], s[1]), fmaxf(s[2 * HS], s[2 * HS + 1]));
        } else {
            v = inA[(size_t)(bt0 + nn) * (CA * HS * HS) + rr];
        }
        sIn[nn * ASZP + c * CSZ + hh * HP + ww] = v;
    }
    __syncthreads();

    const int n   = tid / (GP * PXT);
    const int r   = tid % (GP * PXT);
    const int cog = r / PXT;
    const int p   = r % PXT;
    const int h   = p / (HS / NPIX);
    const int w0  = (p % (HS / NPIX)) * NPIX;
    const float* sI = sIn + n * ASZP;

    float acc[COUT_T][NPIX];
    #pragma unroll
    for (int co = 0; co < COUT_T; co++) {
        float b = sBi[cog * COUT_T + co];
        #pragma unroll
        for (int j = 0; j < NPIX; j++) acc[co][j] = b;
    }

    #pragma unroll 1
    for (int ci = 0; ci < CA; ci++) {
        const float* ch = sI + ci * CSZ;
        #pragma unroll
        for (int kh = 0; kh < 3; kh++) {
            int ih = h + kh - 1;
            bool rowok = (ih >= 0) && (ih < HS);
            float v[NPIX + 2];
            #pragma unroll
            for (int j = 0; j < NPIX + 2; j++) {
                int iw = w0 + j - 1;
                v[j] = (rowok && iw >= 0 && iw < HS) ? ch[ih * HP + iw] : 0.f;
            }
            const float* wr = sW + (ci * 9 + kh * 3) * COUT + cog * COUT_T;
            #pragma unroll
            for (int co = 0; co < COUT_T; co++) {
                float wa = wr[co], wb = wr[COUT + co], wc = wr[2 * COUT + co];
                #pragma unroll
                for (int j = 0; j < NPIX; j++)
                    acc[co][j] = fmaf(wa, v[j], fmaf(wb, v[j + 1], fmaf(wc, v[j + 2], acc[co][j])));
            }
        }
    }

    const int btn = bt0 + n;
    #pragma unroll
    for (int co = 0; co < COUT_T; co++) {
        float* op = out + (size_t)((btn * COUT + cog * COUT_T + co) * HS + h) * HS + w0;
        #pragma unroll
        for (int j = 0; j < NPIX; j += 4)
            *reinterpret_cast<float4*>(op + j) =
                make_float4(fmaxf(acc[co][j], 0.f), fmaxf(acc[co][j + 1], 0.f),
                            fmaxf(acc[co][j + 2], 0.f), fmaxf(acc[co][j + 3], 0.f));
    }
}

// -------------------- decoder conv3x3 over [up2x(A), B] + ReLU ---------------
// A kept at coarse HA=HS/2 (2x2 parity-folded stencil). Padded rows + transposed W.
template<int CA, int CB, int COUT, int COUT_T, int HS, int NBT, int NPIX>
__global__ void __launch_bounds__(256, 2)
conv_up_k(const float* __restrict__ inA, const float* __restrict__ inB,
          const float* __restrict__ wgt, const float* __restrict__ bias,
          float* __restrict__ out)
{
    constexpr int CIN  = CA + CB;
    constexpr int HA   = HS / 2;
    constexpr int HAP  = HA + 1;
    constexpr int HP   = HS + 1;
    constexpr int CASZ = HA * HAP;        // padded coarse channel
    constexpr int CBSZ = HS * HP;         // padded fine channel
    constexpr int ASZP = CA * CASZ;
    constexpr int TSZ  = ASZP + CB * CBSZ;
    constexpr int GP   = COUT / COUT_T;
    constexpr int PXT  = HS * HS / NPIX;
    constexpr int WSZ  = COUT * CIN * 9;
    constexpr int NC   = NPIX / 2 + 2;

    extern __shared__ float sm[];
    float* sW  = sm;                  // transposed [CIN*9][COUT]
    float* sBi = sW + WSZ;
    float* sIn = sBi + COUT;

    const int tid = threadIdx.x, NT = blockDim.x;
    const int bt0 = blockIdx.x * NBT;

    for (int i = tid; i < WSZ; i += NT) {
        int co = i % COUT;
        int rest = i / COUT;
        int ci = rest / 9, kk = rest % 9;
        sW[i] = wgt[(co * CIN + ci) * 9 + kk];
    }
    for (int i = tid; i < COUT; i += NT) sBi[i] = bias[i];
    for (int i = tid; i < NBT * CA * HA * HA; i += NT) {
        int nn = i / (CA * HA * HA), rr = i % (CA * HA * HA);
        int c = rr / (HA * HA), pp = rr % (HA * HA);
        sIn[nn * TSZ + c * CASZ + (pp / HA) * HAP + (pp % HA)] =
            inA[(size_t)(bt0 + nn) * (CA * HA * HA) + rr];
    }
    for (int i = tid; i < NBT * CB * HS * HS; i += NT) {
        int nn = i / (CB * HS * HS), rr = i % (CB * HS * HS);
        int c = rr / (HS * HS), pp = rr % (HS * HS);
        sIn[nn * TSZ + ASZP + c * CBSZ + (pp / HS) * HP + (pp % HS)] =
            inB[(size_t)(bt0 + nn) * (CB * HS * HS) + rr];
    }
    __syncthreads();

    const int n   = tid / (GP * PXT);
    const int r   = tid % (GP * PXT);
    const int cog = r / PXT;
    const int p   = r % PXT;
    const int h   = p / (HS / NPIX);
    const int w0  = (p % (HS / NPIX)) * NPIX;
    const float* sI = sIn + n * TSZ;

    float acc[COUT_T][NPIX];
    #pragma unroll
    for (int co = 0; co < COUT_T; co++) {
        float b = sBi[cog * COUT_T + co];
        #pragma unroll
        for (int j = 0; j < NPIX; j++) acc[co][j] = b;
    }

    // ---- A part: coarse 2x2 stencil with parity-folded weights ----
    const int  a    = h >> 1;
    const bool hodd = (h & 1) != 0;
    const int  rowA = hodd ? a : a - 1;
    const int  rowB = hodd ? a + 1 : a;
    const int  cs0  = (w0 >> 1) - 1;

    #pragma unroll 1
    for (int ci = 0; ci < CA; ci++) {
        const float* ch = sI + ci * CASZ;
        float cAr[NC], cBr[NC];
        #pragma unroll
        for (int k = 0; k < NC; k++) {
            int cc = cs0 + k;
            bool cok = (cc >= 0) && (cc < HA);
            cAr[k] = (cok && rowA >= 0) ? ch[rowA * HAP + cc] : 0.f;
            cBr[k] = (cok && rowB < HA) ? ch[rowB * HAP + cc] : 0.f;
        }
        const float* wr = sW + ci * 9 * COUT + cog * COUT_T;
        #pragma unroll
        for (int co = 0; co < COUT_T; co++) {
            float w00 = wr[0 * COUT + co], w01 = wr[1 * COUT + co], w02 = wr[2 * COUT + co];
            float w10 = wr[3 * COUT + co], w11 = wr[4 * COUT + co], w12 = wr[5 * COUT + co];
            float w20 = wr[6 * COUT + co], w21 = wr[7 * COUT + co], w22 = wr[8 * COUT + co];
            float rA0 = hodd ? (w00 + w10) : w00;
            float rA1 = hodd ? (w01 + w11) : w01;
            float rA2 = hodd ? (w02 + w12) : w02;
            float rB0 = hodd ? w20 : (w10 + w20);
            float rB1 = hodd ? w21 : (w11 + w21);
            float rB2 = hodd ? w22 : (w12 + w22);
            float sA0 = rA0, sA01 = rA0 + rA1, sA12 = rA1 + rA2, sA2 = rA2;
            float sB0 = rB0, sB01 = rB0 + rB1, sB12 = rB1 + rB2, sB2 = rB2;
            #pragma unroll
            for (int j = 0; j < NPIX; j++) {
                int lb = (j >> 1) + 1;
                if ((j & 1) == 0) {
                    acc[co][j] = fmaf(cAr[lb - 1], sA0,  acc[co][j]);
                    acc[co][j] = fmaf(cAr[lb],     sA12, acc[co][j]);
                    acc[co][j] = fmaf(cBr[lb - 1], sB0,  acc[co][j]);
                    acc[co][j] = fmaf(cBr[lb],     sB12, acc[co][j]);
                } else {
                    acc[co][j] = fmaf(cAr[lb],     sA01, acc[co][j]);
                    acc[co][j] = fmaf(cAr[lb + 1], sA2,  acc[co][j]);
                    acc[co][j] = fmaf(cBr[lb],     sB01, acc[co][j]);
                    acc[co][j] = fmaf(cBr[lb + 1], sB2,  acc[co][j]);
                }
            }
        }
    }

    // ---- B part: standard fine 3x3 ----
    #pragma unroll 1
    for (int ci = 0; ci < CB; ci++) {
        const float* ch = sI + ASZP + ci * CBSZ;
        #pragma unroll
        for (int kh = 0; kh < 3; kh++) {
            int ih = h + kh - 1;
            bool rowok = (ih >= 0) && (ih < HS);
            float v[NPIX + 2];
            #pragma unroll
            for (int j = 0; j < NPIX + 2; j++) {
                int iw = w0 + j - 1;
                v[j] = (rowok && iw >= 0 && iw < HS) ? ch[ih * HP + iw] : 0.f;
            }
            const float* wr = sW + ((CA + ci) * 9 + kh * 3) * COUT + cog * COUT_T;
            #pragma unroll
            for (int co = 0; co < COUT_T; co++) {
                float wa = wr[co], wb = wr[COUT + co], wc = wr[2 * COUT + co];
                #pragma unroll
                for (int j = 0; j < NPIX; j++)
                    acc[co][j] = fmaf(wa, v[j], fmaf(wb, v[j + 1], fmaf(wc, v[j + 2], acc[co][j])));
            }
        }
    }

    const int btn = bt0 + n;
    #pragma unroll
    for (int co = 0; co < COUT_T; co++) {
        float* op = out + (size_t)((btn * COUT + cog * COUT_T + co) * HS + h) * HS + w0;
        #pragma unroll
        for (int j = 0; j < NPIX; j += 4)
            *reinterpret_cast<float4*>(op + j) =
                make_float4(fmaxf(acc[co][j], 0.f), fmaxf(acc[co][j + 1], 0.f),
                            fmaxf(acc[co][j + 2], 0.f), fmaxf(acc[co][j + 3], 0.f));
    }
}

// -------------------- 1x1 conv -> softmax(3ch incl. ones) -> masked feat ----
__global__ void mask_feat_kernel(const float* __restrict__ d1, const float* __restrict__ xt,
                                 const float* __restrict__ ow, const float* __restrict__ ob,
                                 float* __restrict__ feat)
{
    int idx = blockIdx.x * blockDim.x + threadIdx.x;
    if (idx >= BT * 1024) return;
    int bt = idx >> 10, hw = idx & 1023;
    const float* dp = d1 + (size_t)bt * 8 * 1024 + hw;
    float l0 = ob[0], l1 = ob[1];
    #pragma unroll
    for (int c = 0; c < 8; c++) {
        float v = dp[(size_t)c << 10];
        l0 = fmaf(v, ow[c], l0);
        l1 = fmaf(v, ow[8 + c], l1);
    }
    float mx = fmaxf(fmaxf(l0, l1), 1.0f);
    float e0 = expf(l0 - mx), e1 = expf(l1 - mx), e2 = expf(1.0f - mx);
    float inv = 1.0f / (e0 + e1 + e2);
    float m0 = e0 * inv, m1 = e1 * inv;

    const float* xp = xt + (size_t)bt * 3 * 1024 + hw;
    float* fp = feat + (size_t)bt * FEAT + hw;
    #pragma unroll
    for (int c = 0; c < 3; c++) {
        float xv = xp[(size_t)c << 10];
        fp[(size_t)c << 10]       = m0 * xv;
        fp[(size_t)(3 + c) << 10] = m1 * xv;
    }
}

// -------------------- tiled SGEMM (full-K, bias+relu) -------------------------
template<int BM, int BN, int BK, int TM, int TN, bool RELU>
__global__ void sgemm_k(int M, int N, int K,
                        const float* __restrict__ A, const float* __restrict__ Bm,
                        const float* __restrict__ bias, float* __restrict__ C)
{
    __shared__ float sA[BK][BM + 1];
    __shared__ float sB[BK][BN];
    const int tid = threadIdx.x;
    const int tx = tid % (BN / TN);
    const int ty = tid / (BN / TN);
    const int bm = blockIdx.y * BM;
    const int bn = blockIdx.x * BN;

    float acc[TM][TN];
    #pragma unroll
    for (int i = 0; i < TM; i++)
        #pragma unroll
        for (int j = 0; j < TN; j++) acc[i][j] = 0.f;

    for (int k0 = 0; k0 < K; k0 += BK) {
        for (int i = tid; i < BM * BK; i += 256) {
            int m = i / BK, kk = i % BK;
            sA[kk][m] = (bm + m < M && k0 + kk < K) ? A[(size_t)(bm + m) * K + k0 + kk] : 0.f;
        }
        for (int i = tid; i < BK * BN; i += 256) {
            int kk = i / BN, n = i % BN;
            sB[kk][n] = (k0 + kk < K && bn + n < N) ? Bm[(size_t)(k0 + kk) * N + bn + n] : 0.f;
        }
        __syncthreads();
        #pragma unroll
        for (int kk = 0; kk < BK; kk++) {
            float a[TM], b[TN];
            #pragma unroll
            for (int i = 0; i < TM; i++) a[i] = sA[kk][ty * TM + i];
            #pragma unroll
            for (int j = 0; j < TN; j++) b[j] = sB[kk][tx * TN + j];
            #pragma unroll
            for (int i = 0; i < TM; i++)
                #pragma unroll
                for (int j = 0; j < TN; j++) acc[i][j] = fmaf(a[i], b[j], acc[i][j]);
        }
        __syncthreads();
    }

    #pragma unroll
    for (int i = 0; i < TM; i++) {
        int m = bm + ty * TM + i;
        if (m >= M) continue;
        #pragma unroll
        for (int j = 0; j < TN; j++) {
            int n = bn + tx * TN + j;
            if (n >= N) continue;
            float v = acc[i][j] + bias[n];
            if (RELU) v = fmaxf(v, 0.f);
            C[(size_t)m * N + n] = v;
        }
    }
}

// -------------------- split-K SGEMM: partial C per blockIdx.z ----------------
template<int BM, int BN, int BK, int TM, int TN>
__global__ void sgemm_split_k(int M, int N, int K, int KS,
                              const float* __restrict__ A, const float* __restrict__ Bm,
                              float* __restrict__ Cpart)
{
    __shared__ float sA[BK][BM + 1];
    __shared__ float sB[BK][BN];
    const int tid = threadIdx.x;
    const int tx = tid % (BN / TN);
    const int ty = tid / (BN / TN);
    const int bm = blockIdx.y * BM;
    const int bn = blockIdx.x * BN;
    const int kbase = blockIdx.z * KS;

    float acc[TM][TN];
    #pragma unroll
    for (int i = 0; i < TM; i++)
        #pragma unroll
        for (int j = 0; j < TN; j++) acc[i][j] = 0.f;

    for (int k0 = kbase; k0 < kbase + KS; k0 += BK) {
        for (int i = tid; i < BM * BK; i += 256) {
            int m = i / BK, kk = i % BK;
            sA[kk][m] = (bm + m < M) ? A[(size_t)(bm + m) * K + k0 + kk] : 0.f;
        }
        for (int i = tid; i < BK * BN; i += 256) {
            int kk = i / BN, n = i % BN;
            sB[kk][n] = (bn + n < N) ? Bm[(size_t)(k0 + kk) * N + bn + n] : 0.f;
        }
        __syncthreads();
        #pragma unroll
        for (int kk = 0; kk < BK; kk++) {
            float a[TM], b[TN];
            #pragma unroll
            for (int i = 0; i < TM; i++) a[i] = sA[kk][ty * TM + i];
            #pragma unroll
            for (int j = 0; j < TN; j++) b[j] = sB[kk][tx * TN + j];
            #pragma unroll
            for (int i = 0; i < TM; i++)
                #pragma unroll
                for (int j = 0; j < TN; j++) acc[i][j] = fmaf(a[i], b[j], acc[i][j]);
        }
        __syncthreads();
    }

    float* Cp = Cpart + (size_t)blockIdx.z * M * N;
    #pragma unroll
    for (int i = 0; i < TM; i++) {
        int m = bm + ty * TM + i;
        if (m >= M) continue;
        #pragma unroll
        for (int j = 0; j < TN; j++) {
            int n = bn + tx * TN + j;
            if (n >= N) continue;
            Cp[(size_t)m * N + n] = acc[i][j];
        }
    }
}

__global__ void reduce4_relu_kernel(const float* __restrict__ part,
                                    const float* __restrict__ bias,
                                    float* __restrict__ out)
{
    int idx = blockIdx.x * blockDim.x + threadIdx.x;
    if (idx >= BT * HID) return;
    int n = idx % HID;
    float v = bias[n] + part[idx] + part[BT * HID + idx]
            + part[2 * BT * HID + idx] + part[3 * BT * HID + idx];
    out[idx] = fmaxf(v, 0.f);
}

// -------------------- final 200->4 + tanh scale ------------------------------
__global__ void loc3_kernel(const float* __restrict__ h2, const float* __restrict__ w3,
                            const float* __restrict__ b3, float* __restrict__ out)
{
    int idx = blockIdx.x * blockDim.x + threadIdx.x;
    if (idx >= BT * 4) return;
    int m = idx >> 2, j = idx & 3;
    float acc = b3[j];
    const float* hp = h2 + (size_t)m * HID;
    #pragma unroll 8
    for (int k = 0; k < HID; k++) acc = fmaf(hp[k], w3[k * 4 + j], acc);
    out[idx] = tanhf(acc) * 16.f + 16.f;
}

// -------------------- launch --------------------------------------------------
extern "C" void kernel_launch(void* const* d_in, const int* in_sizes, int n_in,
                              void* d_out, int out_size)
{
    const float* x   = (const float*)d_in[0];
    const float* ew1 = (const float*)d_in[1];
    const float* eb1 = (const float*)d_in[2];
    const float* ew2 = (const float*)d_in[3];
    const float* eb2 = (const float*)d_in[4];
    const float* ew3 = (const float*)d_in[5];
    const float* eb3 = (const float*)d_in[6];
    const float* dw2 = (const float*)d_in[7];
    const float* db2 = (const float*)d_in[8];
    const float* dw1 = (const float*)d_in[9];
    const float* db1 = (const float*)d_in[10];
    const float* ow  = (const float*)d_in[11];
    const float* ob  = (const float*)d_in[12];
    const float* lw1 = (const float*)d_in[13];
    const float* lb1 = (const float*)d_in[14];
    const float* lw2 = (const float*)d_in[15];
    const float* lb2 = (const float*)d_in[16];
    const float* lw3 = (const float*)d_in[17];
    const float* lb3 = (const float*)d_in[18];
    float* out = (float*)d_out;

    float *xt, *e1, *e2, *e3, *d2v, *d1v, *feat, *h1, *h2, *part;
    cudaGetSymbolAddress((void**)&xt,   g_xt);
    cudaGetSymbolAddress((void**)&e1,   g_e1);
    cudaGetSymbolAddress((void**)&e2,   g_e2);
    cudaGetSymbolAddress((void**)&e3,   g_e3);
    cudaGetSymbolAddress((void**)&d2v,  g_d2);
    cudaGetSymbolAddress((void**)&d1v,  g_d1);
    cudaGetSymbolAddress((void**)&feat, g_feat);
    cudaGetSymbolAddress((void**)&h1,   g_h1);
    cudaGetSymbolAddress((void**)&h2,   g_h2);
    cudaGetSymbolAddress((void**)&part, g_part);

    // smem bytes (padded layouts)
    constexpr int SM_E1 = (3 * 8 * 9  + 8  + 2 * 3 * 32 * 33) * 4;                    // 26240
    constexpr int SM_E2 = (8 * 16 * 9 + 16 + 4 * 8 * 16 * 17) * 4;                    // 39488
    constexpr int SM_E3 = (16 * 32 * 9 + 32 + 8 * 16 * 8 * 9) * 4;                    // 55424
    constexpr int SM_D2 = (48 * 16 * 9 + 16 + 2 * (32 * 8 * 9 + 16 * 16 * 17)) * 4;   // 80960
    constexpr int SM_D1 = (24 * 8 * 9 + 8 + 2 * (16 * 16 * 17 + 8 * 32 * 33)) * 4;    // 109344

    cudaFuncSetAttribute((const void*)conv_std_k<8, 16, 8, 16, 4, 8, true>,
                         cudaFuncAttributeMaxDynamicSharedMemorySize, SM_E2);
    cudaFuncSetAttribute((const void*)conv_std_k<16, 32, 8, 8, 8, 8, true>,
                         cudaFuncAttributeMaxDynamicSharedMemorySize, SM_E3);
    cudaFuncSetAttribute((const void*)conv_up_k<32, 16, 16, 4, 16, 2, 8>,
                         cudaFuncAttributeMaxDynamicSharedMemorySize, SM_D2);
    cudaFuncSetAttribute((const void*)conv_up_k<16, 8, 8, 8, 32, 2, 8>,
                         cudaFuncAttributeMaxDynamicSharedMemorySize, SM_D1);

    // 1) permute
    permute_kernel<<<32 * 3 * 32, 256>>>(x, xt);
    // 2) e1 = relu(conv 3->8 @32)
    conv_std_k<3, 8, 8, 32, 2, 8, false><<<BT / 2, 256, SM_E1>>>(xt, ew1, eb1, e1);
    // 3) e2 = relu(conv pool(e1) 8->16 @16)
    conv_std_k<8, 16, 8, 16, 4, 8, true><<<BT / 4, 256, SM_E2>>>(e1, ew2, eb2, e2);
    // 4) e3 = relu(conv pool(e2) 16->32 @8)
    conv_std_k<16, 32, 8, 8, 8, 8, true><<<BT / 8, 256, SM_E3>>>(e2, ew3, eb3, e3);
    // 5) d2 = relu(conv [up(e3), e2] 48->16 @16)
    conv_up_k<32, 16, 16, 4, 16, 2, 8><<<BT / 2, 256, SM_D2>>>(e3, e2, dw2, db2, d2v);
    // 6) d1 = relu(conv [up(d2), e1] 24->8 @32)
    conv_up_k<16, 8, 8, 8, 32, 2, 8><<<BT / 2, 256, SM_D1>>>(d2v, e1, dw1, db1, d1v);
    // 7) masks + masked features
    mask_feat_kernel<<<(BT * 1024) / 256, 256>>>(d1v, xt, ow, ob, feat);
    // 8) h1 = relu(feat @ lw1 + lb1) via split-K x4
    sgemm_split_k<64, 64, 16, 4, 4><<<dim3(4, BT / 64, 4), 256>>>(BT, HID, FEAT, FEAT / 4, feat, lw1, part);
    reduce4_relu_kernel<<<(BT * HID + 255) / 256, 256>>>(part, lb1, h1);
    // 9) h2 = relu(h1 @ lw2 + lb2)
    sgemm_k<64, 64, 16, 4, 4, true><<<dim3(4, BT / 64), 256>>>(BT, HID, HID, h1, lw2, lb2, h2);
    // 10) out = tanh(h2 @ lw3 + lb3)*16+16
    loc3_kernel<<<(BT * 4 + 255) / 256, 256>>>(h2, lw3, lb3, out);
}